// round 17
// baseline (speedup 1.0000x reference)
#include <cuda_runtime.h>
#include <cuda_fp16.h>

#define ALPHA 0.2f
#define B_TOT 65536

typedef unsigned int u32;
typedef unsigned long long u64;

// ---- persistent prepped constants ----
__device__ float d_wa1[128];
// W pre-shuffled into m16n8k16 B-fragment order:
// index = ((qw*2 + np)*8 + ks)*32 + lane, each entry = the 4 u32 regs ldsm4 would yield.
__device__ uint4 d_Wfrag[2048];   // 32 KB

__global__ void prep_kernel(const float* __restrict__ W, const float* __restrict__ a) {
    int blk = blockIdx.x, tid = threadIdx.x;
    if (blk < 64) {
        if (tid < 32) {
            int qw = blk >> 4, np = (blk >> 3) & 1, ks = blk & 7;
            int l = tid;
            int n0 = qw * 32 + np * 16 + (l >> 2);
            int k0 = ks * 16 + (l & 3) * 2;
            __half2 p0 = __floats2half2_rn(W[k0 * 128 + n0],        W[(k0 + 1) * 128 + n0]);
            __half2 p1 = __floats2half2_rn(W[(k0 + 8) * 128 + n0],  W[(k0 + 9) * 128 + n0]);
            __half2 p2 = __floats2half2_rn(W[k0 * 128 + n0 + 8],    W[(k0 + 1) * 128 + n0 + 8]);
            __half2 p3 = __floats2half2_rn(W[(k0 + 8) * 128 + n0 + 8], W[(k0 + 9) * 128 + n0 + 8]);
            uint4 v;
            v.x = *(u32*)&p0; v.y = *(u32*)&p1; v.z = *(u32*)&p2; v.w = *(u32*)&p3;
            d_Wfrag[blk * 32 + l] = v;
        }
    } else if (tid < 32) {
        int f = blk - 64;
        float4 wv = *(const float4*)(W + f * 128 + tid * 4);
        float4 av = *(const float4*)(a + tid * 4);
        float p = wv.x * av.x + wv.y * av.y + wv.z * av.z + wv.w * av.w;
#pragma unroll
        for (int off = 16; off; off >>= 1) p += __shfl_xor_sync(0xFFFFFFFFu, p, off);
        if (tid == 0) d_wa1[f] = p;
    }
}

// ---- smem: two quad A panels, rows padded to 272B for conflict-free ldmatrix ----
#define ROWB 272
#define PANELB 8704
#define SMEM_BYTES (2 * PANELB)   // 17408

__device__ __forceinline__ u32 smem_u32(const void* p) {
    u32 a;
    asm("{ .reg .u64 t; cvta.to.shared.u64 t, %1; cvt.u32.u64 %0, t; }" : "=r"(a) : "l"(p));
    return a;
}
__device__ __forceinline__ void ldsm4(u32* r, u32 addr) {
    asm volatile("ldmatrix.sync.aligned.m8n8.x4.shared.b16 {%0,%1,%2,%3}, [%4];"
                 : "=r"(r[0]), "=r"(r[1]), "=r"(r[2]), "=r"(r[3]) : "r"(addr));
}
__device__ __forceinline__ void mma16816(float* c, const u32* a, u32 b0, u32 b1) {
    asm volatile("mma.sync.aligned.m16n8k16.row.col.f32.f16.f16.f32 "
                 "{%0,%1,%2,%3}, {%4,%5,%6,%7}, {%8,%9}, {%0,%1,%2,%3};"
                 : "+f"(c[0]), "+f"(c[1]), "+f"(c[2]), "+f"(c[3])
                 : "r"(a[0]), "r"(a[1]), "r"(a[2]), "r"(a[3]), "r"(b0), "r"(b1));
}
// ---- packed f32x2 helpers (sm_103; validated in R1) ----
__device__ __forceinline__ u64 pack2(float x, float y) {
    u64 d; asm("mov.b64 %0, {%1, %2};" : "=l"(d) : "f"(x), "f"(y)); return d;
}
__device__ __forceinline__ u64 fma2(u64 a, u64 b, u64 c) {
    u64 d; asm("fma.rn.f32x2 %0, %1, %2, %3;" : "=l"(d) : "l"(a), "l"(b), "l"(c)); return d;
}
__device__ __forceinline__ u64 mul2(u64 a, u64 b) {
    u64 d; asm("mul.rn.f32x2 %0, %1, %2;" : "=l"(d) : "l"(a), "l"(b)); return d;
}
__device__ __forceinline__ float2 unpack2(u64 v) {
    float2 r; asm("mov.b64 {%0, %1}, %2;" : "=f"(r.x), "=f"(r.y) : "l"(v)); return r;
}

// attention + fold for ONE batch; writes 8 fp16 rows of the quad A panel
__device__ __forceinline__ void attention_fold(
    const float4* hv, const float* __restrict__ adjb,
    float4 an, float4 v1, int lane, char* Ah, int row_base)
{
    // hoisted adj row-0 loads (DRAM latency hidden under the whole reduction)
    const float4* adj4 = (const float4*)adjb;
    float4 A0 = adj4[0], A1 = adj4[1];

    // ---- 16 simultaneous 128-dim dots: halving-exchange multi-value reduction ----
    float vals[16];
#pragma unroll
    for (int j = 0; j < 8; j++) {
        vals[j]     = hv[j].x * an.x + hv[j].y * an.y + hv[j].z * an.z + hv[j].w * an.w;
        vals[8 + j] = hv[j].x * v1.x + hv[j].y * v1.y + hv[j].z * v1.z + hv[j].w * v1.w;
    }
#pragma unroll
    for (int i = 0; i < 8; i++) {      // stage m=16
        bool hi = (lane & 16) != 0;
        float snd = hi ? vals[i] : vals[i + 8];
        float kp  = hi ? vals[i + 8] : vals[i];
        vals[i] = kp + __shfl_xor_sync(0xFFFFFFFFu, snd, 16);
    }
#pragma unroll
    for (int i = 0; i < 4; i++) {      // stage m=8
        bool hi = (lane & 8) != 0;
        float snd = hi ? vals[i] : vals[i + 4];
        float kp  = hi ? vals[i + 4] : vals[i];
        vals[i] = kp + __shfl_xor_sync(0xFFFFFFFFu, snd, 8);
    }
#pragma unroll
    for (int i = 0; i < 2; i++) {      // stage m=4
        bool hi = (lane & 4) != 0;
        float snd = hi ? vals[i] : vals[i + 2];
        float kp  = hi ? vals[i + 2] : vals[i];
        vals[i] = kp + __shfl_xor_sync(0xFFFFFFFFu, snd, 4);
    }
    {                                   // stage m=2
        bool hi = (lane & 2) != 0;
        float snd = hi ? vals[0] : vals[1];
        float kp  = hi ? vals[1] : vals[0];
        vals[0] = kp + __shfl_xor_sync(0xFFFFFFFFu, snd, 2);
    }
    vals[0] += __shfl_xor_sync(0xFFFFFFFFu, vals[0], 1);   // final m=1
    float en[8], s1[8];
#pragma unroll
    for (int j = 0; j < 8; j++) {
        en[j] = __shfl_sync(0xFFFFFFFFu, vals[0], 2 * j);
        s1[j] = __shfl_sync(0xFFFFFFFFu, vals[0], 16 + 2 * j);
    }

    // ---- node softmax (leaky; logits |x|<~3, raw exp safe) + residual scale ----
    float sum = 0.f;
#pragma unroll
    for (int j = 0; j < 8; j++) {
        float v = en[j] > 0.f ? en[j] : ALPHA * en[j];
        float p = __expf(v);
        en[j] = p;
        sum += p;
    }
    float inv = 1.f / sum;
    float scale[8], u[8], w[8];
#pragma unroll
    for (int j = 0; j < 8; j++) {
        float sc = 1.f + en[j] * inv;
        scale[j] = sc;
        u[j] = __expf(sc * s1[j]);     // Wh2[i] cancels in the row softmax
        w[j] = u[j] * scale[j];
    }

    // packed h pairs (K-dim): hp[2j] = {h.x, h.y}, hp[2j+1] = {h.z, h.w}
    u64 hp[16];
#pragma unroll
    for (int j = 0; j < 8; j++) {
        hp[2 * j]     = pack2(hv[j].x, hv[j].y);
        hp[2 * j + 1] = pack2(hv[j].z, hv[j].w);
    }

#pragma unroll
    for (int i = 0; i < 8; i++) {
        float adv[8] = {A0.x, A0.y, A0.z, A0.w, A1.x, A1.y, A1.z, A1.w};
        if (i < 7) { A0 = adj4[2 * (i + 1)]; A1 = adj4[2 * (i + 1) + 1]; }

        float s = adv[0] * u[0];
        s = fmaf(adv[1], u[1], s); s = fmaf(adv[2], u[2], s); s = fmaf(adv[3], u[3], s);
        s = fmaf(adv[4], u[4], s); s = fmaf(adv[5], u[5], s); s = fmaf(adv[6], u[6], s);
        s = fmaf(adv[7], u[7], s);
        float c[8], is;
        if (s != 0.f) {                       // warp-uniform branch
            is = __fdividef(1.f, s);
#pragma unroll
            for (int j = 0; j < 8; j++) c[j] = adv[j] * w[j];
        } else {                              // fully-masked row: uniform 1/8
            is = 0.125f;
#pragma unroll
            for (int j = 0; j < 8; j++) c[j] = scale[j];
        }

        // packed f32x2 fold: per-element chain identical to scalar version
        u64 acc0 = 0ull, acc1 = 0ull;
#pragma unroll
        for (int j = 0; j < 8; j++) {
            u64 cc = pack2(c[j], c[j]);
            acc0 = fma2(cc, hp[2 * j],     acc0);
            acc1 = fma2(cc, hp[2 * j + 1], acc1);
        }
        u64 isv = pack2(is, is);
        acc0 = mul2(acc0, isv);
        acc1 = mul2(acc1, isv);
        float2 g01 = unpack2(acc0), g23 = unpack2(acc1);

        __half2 h01 = __floats2half2_rn(g01.x, g01.y);
        __half2 h23 = __floats2half2_rn(g23.x, g23.y);
        uint2 uh = make_uint2(*(u32*)&h01, *(u32*)&h23);
        *(uint2*)(Ah + (row_base + i) * ROWB + lane * 8) = uh;
    }
}

__global__ __launch_bounds__(256, 3) void fused_gat_hmma(
    const float* __restrict__ h, const float* __restrict__ adj,
    const float* __restrict__ a_node, float* __restrict__ out)
{
    extern __shared__ char sm[];
    const u32 smb = smem_u32(sm);
    int tid = threadIdx.x, lane = tid & 31, warp = tid >> 5;
    int quad = warp >> 2, qw = warp & 3;     // 2 quads/CTA, 4 warps each

    const int bq = blockIdx.x * 8 + quad * 4;   // quad's first batch
    const int b = bq + qw;                      // this warp's batch

    // ---- this batch's h loads issued first ----
    float4 hv[8];
    {
        const float* hb = h + (size_t)b * 1024;
#pragma unroll
        for (int j = 0; j < 8; j++) hv[j] = *(const float4*)(hb + j * 128 + lane * 4);
    }

    float4 an = *(const float4*)(a_node + lane * 4);
    float4 v1 = *(const float4*)(d_wa1 + lane * 4);

    char* Ah = sm + quad * PANELB;   // 32 rows = quad's 4 batches
    const int rb = qw * 8;

    attention_fold(hv, adj + (size_t)b * 64, an, v1, lane, Ah, rb);

    // quad barrier: all 4 warps' A rows visible before cross-read
    asm volatile("bar.sync %0, 128;" :: "r"(quad + 1) : "memory");

    // ====== HMMA GEMM: rows 0..31 (quad's 4 batches) x this warp's 32-col quarter ======
    float acc[8][4];   // [mt*4+nt][c]
#pragma unroll
    for (int t = 0; t < 8; t++) { acc[t][0] = acc[t][1] = acc[t][2] = acc[t][3] = 0.f; }

    const u32 ah_base = smb + (u32)(quad * PANELB);
    const u32 a_off = (u32)((lane & 15) * ROWB + (lane >> 4) * 16);
    const uint4* __restrict__ Wf = d_Wfrag + (size_t)qw * 512 + lane;

#pragma unroll
    for (int ks = 0; ks < 8; ks++) {
        u32 afh[2][4];
#pragma unroll
        for (int mt = 0; mt < 2; mt++)
            ldsm4(afh[mt], ah_base + a_off + mt * (16 * ROWB) + ks * 32);
#pragma unroll
        for (int np = 0; np < 2; np++) {
            uint4 bh = __ldg(Wf + (np * 8 + ks) * 32);
#pragma unroll
            for (int mt = 0; mt < 2; mt++) {
                mma16816(acc[mt * 4 + 2 * np],     afh[mt], bh.x, bh.y);
                mma16816(acc[mt * 4 + 2 * np + 1], afh[mt], bh.z, bh.w);
            }
        }
    }

    // ---- epilogue: relu + store ----
#pragma unroll
    for (int mt = 0; mt < 2; mt++) {
        float* o0 = out + ((size_t)(bq + mt * 2) * 8 + (lane >> 2)) * 128 +
                    qw * 32 + (lane & 3) * 2;
        float* o1 = o0 + 1024;
#pragma unroll
        for (int nt = 0; nt < 4; nt++) {
            float* ac = acc[mt * 4 + nt];
            float2 r0 = make_float2(fmaxf(ac[0], 0.f), fmaxf(ac[1], 0.f));
            float2 r1 = make_float2(fmaxf(ac[2], 0.f), fmaxf(ac[3], 0.f));
            *(float2*)(o0 + nt * 8) = r0;
            *(float2*)(o1 + nt * 8) = r1;
        }
    }
}

extern "C" void kernel_launch(void* const* d_in, const int* in_sizes, int n_in,
                              void* d_out, int out_size) {
    const float* h      = (const float*)d_in[0];
    const float* adj    = (const float*)d_in[1];
    const float* W      = (const float*)d_in[2];
    const float* a      = (const float*)d_in[3];
    const float* a_node = (const float*)d_in[4];
    float* out = (float*)d_out;

    prep_kernel<<<192, 256>>>(W, a);

    cudaFuncSetAttribute(fused_gat_hmma, cudaFuncAttributeMaxDynamicSharedMemorySize, SMEM_BYTES);
    fused_gat_hmma<<<B_TOT / 8, 256, SMEM_BYTES>>>(h, adj, a_node, out);
}